// round 4
// baseline (speedup 1.0000x reference)
#include <cuda_runtime.h>
#include <cuda_fp16.h>
#include <cstdint>
#include <cstddef>

// ============================================================================
// GhostLinear: y[M=4096, N=8192] = x[M, K=2048] @ (LUT[gidx]*scale)[N, K]^T
// Target is base sm_100 (harness compiles without 'a' suffix -> tcgen05
// unavailable). Portable tensor path: mma.sync.m16n8k16 fp16 + ldmatrix +
// cp.async 4-stage pipeline.
// ============================================================================

#define GEMM_M 4096
#define GEMM_N 8192
#define GEMM_K 2048

#define BM 128
#define BN 128
#define BK 64
#define STAGES 4
#define NKTILES (GEMM_K / BK)              // 32

#define A_STAGE_BYTES (BM * BK * 2)        // 16384
#define B_STAGE_BYTES (BN * BK * 2)        // 16384
#define STAGE_BYTES   (A_STAGE_BYTES + B_STAGE_BYTES)   // 32768
#define SMEM_BYTES    (STAGES * STAGE_BYTES)            // 131072

// ---- scratch (static device arrays are allowed; no runtime allocs) ----
__device__ __align__(1024) __half g_xh[(size_t)GEMM_M * GEMM_K];   // 16 MB
__device__ __align__(1024) __half g_wh[(size_t)GEMM_N * GEMM_K];   // 32 MB

__constant__ float c_lut[16] = {
    -1.0f, -0.5f, -0.333333f, -0.2f, -0.142857f, -0.090909f, -0.076923f,
     0.0f,  0.076923f, 0.090909f, 0.142857f, 0.2f, 0.333333f, 0.5f, 1.0f, 0.0f};

// ============================================================================
// PTX helpers (all base-ISA sm_80 features, valid on sm_100)
// ============================================================================
__device__ __forceinline__ uint32_t smem_u32(const void* p) {
    uint32_t a;
    asm("{ .reg .u64 t; cvta.to.shared.u64 t, %1; cvt.u32.u64 %0, t; }"
        : "=r"(a) : "l"(p));
    return a;
}

__device__ __forceinline__ void cp_async16(uint32_t dst, const void* src) {
    asm volatile("cp.async.cg.shared.global [%0], [%1], 16;"
                 :: "r"(dst), "l"(src) : "memory");
}
#define CP_COMMIT() asm volatile("cp.async.commit_group;" ::: "memory")
#define CP_WAIT(n)  asm volatile("cp.async.wait_group %0;" :: "n"(n) : "memory")

#define LDSM_X4(R0, R1, R2, R3, ADDR) \
    asm volatile("ldmatrix.sync.aligned.m8n8.x4.shared.b16 {%0,%1,%2,%3}, [%4];" \
                 : "=r"(R0), "=r"(R1), "=r"(R2), "=r"(R3) : "r"(ADDR))

__device__ __forceinline__ void mma16816(float* c, const uint32_t* a,
                                         const uint32_t* b) {
    asm volatile(
        "mma.sync.aligned.m16n8k16.row.col.f32.f16.f16.f32 "
        "{%0,%1,%2,%3}, {%4,%5,%6,%7}, {%8,%9}, {%0,%1,%2,%3};"
        : "+f"(c[0]), "+f"(c[1]), "+f"(c[2]), "+f"(c[3])
        : "r"(a[0]), "r"(a[1]), "r"(a[2]), "r"(a[3]), "r"(b[0]), "r"(b[1]));
}

// ============================================================================
// Prepass kernels: fp32->fp16 x, int32 LUT-dequant -> fp16 w
// ============================================================================
__global__ void gl_convert_x(const float* __restrict__ x) {
    size_t i = (size_t)blockIdx.x * blockDim.x + threadIdx.x;  // one float4 each
    float4 v = reinterpret_cast<const float4*>(x)[i];
    __half2 h0 = __floats2half2_rn(v.x, v.y);
    __half2 h1 = __floats2half2_rn(v.z, v.w);
    uint2 o;
    o.x = *reinterpret_cast<uint32_t*>(&h0);
    o.y = *reinterpret_cast<uint32_t*>(&h1);
    reinterpret_cast<uint2*>(g_xh)[i] = o;
}

__global__ void gl_dequant_w(const int* __restrict__ g,
                             const float* __restrict__ scale_p) {
    float s = __ldg(scale_p);
    size_t i = (size_t)blockIdx.x * blockDim.x + threadIdx.x;  // one int4 each
    int4 v = reinterpret_cast<const int4*>(g)[i];
    __half2 h0 = __floats2half2_rn(c_lut[v.x] * s, c_lut[v.y] * s);
    __half2 h1 = __floats2half2_rn(c_lut[v.z] * s, c_lut[v.w] * s);
    uint2 o;
    o.x = *reinterpret_cast<uint32_t*>(&h0);
    o.y = *reinterpret_cast<uint32_t*>(&h1);
    reinterpret_cast<uint2*>(g_wh)[i] = o;
}

// ============================================================================
// GEMM: 256 threads, 8 warps (2 along M x 4 along N), warp tile 64x32.
// Smem tiles [row][64 halfs] = 128B rows; 16B-chunk XOR swizzle
// (chunk ^= row&7) -> conflict-free cp.async stores AND ldmatrix reads.
// ============================================================================
__device__ __forceinline__ void load_stage(uint32_t sbase, int stage, int kt,
                                           int m0, int n0, int tid) {
    const uint32_t sa = sbase + stage * STAGE_BYTES;
    const uint32_t sB = sa + A_STAGE_BYTES;
    const int k0 = kt * BK;
#pragma unroll
    for (int i = 0; i < 4; i++) {
        int e = i * 256 + tid;            // 0..1023
        int row = e >> 3;                 // 0..127
        int ch  = e & 7;                  // 16B chunk within 128B row
        uint32_t soff = row * 128 + ((ch ^ (row & 7)) << 4);
        cp_async16(sa + soff, &g_xh[(size_t)(m0 + row) * GEMM_K + k0 + ch * 8]);
        cp_async16(sB + soff, &g_wh[(size_t)(n0 + row) * GEMM_K + k0 + ch * 8]);
    }
}

__global__ void __launch_bounds__(256, 1)
gl_gemm(float* __restrict__ out) {
    extern __shared__ __align__(1024) char smem[];
    const uint32_t sbase = smem_u32(smem);
    const int tid  = threadIdx.x;
    const int wid  = tid >> 5;
    const int lane = tid & 31;
    const int m0 = blockIdx.y * BM;
    const int n0 = blockIdx.x * BN;
    const int warp_m = (wid >> 2) * 64;   // 0 or 64
    const int warp_n = (wid & 3) * 32;    // 0, 32, 64, 96

    float acc[4][4][4];
#pragma unroll
    for (int t = 0; t < 4; t++)
#pragma unroll
        for (int u = 0; u < 4; u++)
#pragma unroll
            for (int v = 0; v < 4; v++) acc[t][u][v] = 0.0f;

    // ---- prologue: fill 3 of 4 stages ----
#pragma unroll
    for (int s = 0; s < STAGES - 1; s++) {
        load_stage(sbase, s, s, m0, n0, tid);
        CP_COMMIT();
    }

    // ---- mainloop ----
#pragma unroll 1
    for (int j = 0; j < NKTILES; j++) {
        CP_WAIT(2);          // >=1 of the 3 pending groups drained -> stage j done
        __syncthreads();     // make all threads' cp.async data visible

        const uint32_t sa = sbase + (j & 3) * STAGE_BYTES;
        const uint32_t sB = sa + A_STAGE_BYTES;

#pragma unroll
        for (int ks = 0; ks < 4; ks++) {
            // A fragments: 4 x (m16 x k16) via ldmatrix.x4
            uint32_t a[4][4];
            {
                const int r15 = lane & 15;
                const int ch  = ks * 2 + (lane >> 4);
#pragma unroll
                for (int t = 0; t < 4; t++) {
                    const int row = warp_m + t * 16 + r15;
                    const uint32_t addr =
                        sa + row * 128 + ((ch ^ (row & 7)) << 4);
                    LDSM_X4(a[t][0], a[t][1], a[t][2], a[t][3], addr);
                }
            }
            // B fragments: 4 x (n8 x k16); two n8-tiles per ldmatrix.x4
            uint32_t b[4][2];
            {
                const int nr = (lane & 7) + ((lane >> 4) << 3);
                const int ch = ks * 2 + ((lane >> 3) & 1);
#pragma unroll
                for (int p = 0; p < 2; p++) {
                    const int row = warp_n + p * 16 + nr;
                    const uint32_t addr =
                        sB + row * 128 + ((ch ^ (row & 7)) << 4);
                    LDSM_X4(b[2 * p][0], b[2 * p][1],
                            b[2 * p + 1][0], b[2 * p + 1][1], addr);
                }
            }
            // 16 MMAs
#pragma unroll
            for (int t = 0; t < 4; t++)
#pragma unroll
                for (int u = 0; u < 4; u++)
                    mma16816(acc[t][u], a[t], b[u]);
        }

        // Load next stage if any, then ALWAYS commit (possibly-empty group).
        // Keeps the pending-group count at 3 through the tail so CP_WAIT(2)
        // above still guarantees stage-j completion in the last iterations.
        if (j + STAGES - 1 < NKTILES)
            load_stage(sbase, (j + STAGES - 1) & 3, j + STAGES - 1, m0, n0, tid);
        CP_COMMIT();
    }

    // ---- epilogue: direct fp32 stores (float2, 32B-sector aligned) ----
    const int gq = lane >> 2;            // 0..7 (row within m16 tile)
    const int tq = lane & 3;             // 0..3 (col pair)
#pragma unroll
    for (int t = 0; t < 4; t++) {
#pragma unroll
        for (int u = 0; u < 4; u++) {
            const int r = m0 + warp_m + t * 16 + gq;
            const int c = n0 + warp_n + u * 8 + tq * 2;
            float2 v0 = make_float2(acc[t][u][0], acc[t][u][1]);
            float2 v1 = make_float2(acc[t][u][2], acc[t][u][3]);
            *reinterpret_cast<float2*>(&out[(size_t)r * GEMM_N + c]) = v0;
            *reinterpret_cast<float2*>(&out[(size_t)(r + 8) * GEMM_N + c]) = v1;
        }
    }
}

// ============================================================================
// Host side — no driver API, no tensormaps, nothing that can fail or hang.
// ============================================================================
extern "C" void kernel_launch(void* const* d_in, const int* in_sizes, int n_in,
                              void* d_out, int out_size) {
    const float* x     = (const float*)d_in[0];
    const int*   gidx  = (const int*)d_in[1];
    const float* scale = (const float*)d_in[2];
    float*       out   = (float*)d_out;

    // 1) prepass
    gl_convert_x<<<(GEMM_M * GEMM_K / 4) / 256, 256>>>(x);
    gl_dequant_w<<<(GEMM_N * GEMM_K / 4) / 256, 256>>>(gidx, scale);

    // 2) GEMM
    cudaFuncSetAttribute(gl_gemm, cudaFuncAttributeMaxDynamicSharedMemorySize,
                         SMEM_BYTES);
    dim3 grid(GEMM_N / BN, GEMM_M / BM);  // (64, 32)
    gl_gemm<<<grid, 256, SMEM_BYTES>>>(out);
}

// round 5
// speedup vs baseline: 1.1364x; 1.1364x over previous
#include <cuda_runtime.h>
#include <cuda_fp16.h>
#include <cstdint>
#include <cstddef>

// ============================================================================
// GhostLinear: y[M=4096, N=8192] = x[M, K=2048] @ (LUT[gidx]*scale)[N, K]^T
// Base sm_100 target (no tcgen05). mma.sync.m16n8k16 fp16 + ldmatrix +
// cp.async. R4: CTA tile 128x256, warp tile 64x64, 4 stages, load-first order.
// ============================================================================

#define GEMM_M 4096
#define GEMM_N 8192
#define GEMM_K 2048

#define BM 128
#define BN 256
#define BK 64
#define STAGES 4
#define NKTILES (GEMM_K / BK)              // 32

#define A_STAGE_BYTES (BM * BK * 2)        // 16384
#define B_STAGE_BYTES (BN * BK * 2)        // 32768
#define STAGE_BYTES   (A_STAGE_BYTES + B_STAGE_BYTES)   // 49152
#define SMEM_BYTES    (STAGES * STAGE_BYTES)            // 196608

// ---- scratch (static device arrays are allowed; no runtime allocs) ----
__device__ __align__(1024) __half g_xh[(size_t)GEMM_M * GEMM_K];   // 16 MB
__device__ __align__(1024) __half g_wh[(size_t)GEMM_N * GEMM_K];   // 32 MB

__constant__ float c_lut[16] = {
    -1.0f, -0.5f, -0.333333f, -0.2f, -0.142857f, -0.090909f, -0.076923f,
     0.0f,  0.076923f, 0.090909f, 0.142857f, 0.2f, 0.333333f, 0.5f, 1.0f, 0.0f};

// ============================================================================
// PTX helpers (base-ISA sm_80 features, valid on sm_100)
// ============================================================================
__device__ __forceinline__ uint32_t smem_u32(const void* p) {
    uint32_t a;
    asm("{ .reg .u64 t; cvta.to.shared.u64 t, %1; cvt.u32.u64 %0, t; }"
        : "=r"(a) : "l"(p));
    return a;
}

__device__ __forceinline__ void cp_async16(uint32_t dst, const void* src) {
    asm volatile("cp.async.cg.shared.global [%0], [%1], 16;"
                 :: "r"(dst), "l"(src) : "memory");
}
#define CP_COMMIT() asm volatile("cp.async.commit_group;" ::: "memory")
#define CP_WAIT(n)  asm volatile("cp.async.wait_group %0;" :: "n"(n) : "memory")

#define LDSM_X4(R0, R1, R2, R3, ADDR) \
    asm volatile("ldmatrix.sync.aligned.m8n8.x4.shared.b16 {%0,%1,%2,%3}, [%4];" \
                 : "=r"(R0), "=r"(R1), "=r"(R2), "=r"(R3) : "r"(ADDR))

__device__ __forceinline__ void mma16816(float* c, const uint32_t* a,
                                         const uint32_t* b) {
    asm volatile(
        "mma.sync.aligned.m16n8k16.row.col.f32.f16.f16.f32 "
        "{%0,%1,%2,%3}, {%4,%5,%6,%7}, {%8,%9}, {%0,%1,%2,%3};"
        : "+f"(c[0]), "+f"(c[1]), "+f"(c[2]), "+f"(c[3])
        : "r"(a[0]), "r"(a[1]), "r"(a[2]), "r"(a[3]), "r"(b[0]), "r"(b[1]));
}

// ============================================================================
// Prepass kernels: fp32->fp16 x, int32 LUT-dequant -> fp16 w
// ============================================================================
__global__ void gl_convert_x(const float* __restrict__ x) {
    size_t i = (size_t)blockIdx.x * blockDim.x + threadIdx.x;  // one float4 each
    float4 v = reinterpret_cast<const float4*>(x)[i];
    __half2 h0 = __floats2half2_rn(v.x, v.y);
    __half2 h1 = __floats2half2_rn(v.z, v.w);
    uint2 o;
    o.x = *reinterpret_cast<uint32_t*>(&h0);
    o.y = *reinterpret_cast<uint32_t*>(&h1);
    reinterpret_cast<uint2*>(g_xh)[i] = o;
}

__global__ void gl_dequant_w(const int* __restrict__ g,
                             const float* __restrict__ scale_p) {
    float s = __ldg(scale_p);
    size_t i = (size_t)blockIdx.x * blockDim.x + threadIdx.x;  // one int4 each
    int4 v = reinterpret_cast<const int4*>(g)[i];
    __half2 h0 = __floats2half2_rn(c_lut[v.x] * s, c_lut[v.y] * s);
    __half2 h1 = __floats2half2_rn(c_lut[v.z] * s, c_lut[v.w] * s);
    uint2 o;
    o.x = *reinterpret_cast<uint32_t*>(&h0);
    o.y = *reinterpret_cast<uint32_t*>(&h1);
    reinterpret_cast<uint2*>(g_wh)[i] = o;
}

// ============================================================================
// GEMM: 256 threads, 8 warps (2 along M x 4 along N), warp tile 64x64.
// Smem tiles [row][64 halfs] = 128B rows; 16B-chunk XOR swizzle
// (chunk ^= row&7) -> conflict-free cp.async stores AND ldmatrix reads.
// ============================================================================
__device__ __forceinline__ void load_stage(uint32_t sbase, int stage, int kt,
                                           int m0, int n0, int tid) {
    const uint32_t sa = sbase + stage * STAGE_BYTES;
    const uint32_t sB = sa + A_STAGE_BYTES;
    const int k0 = kt * BK;
    // A: 128 rows x 8 chunks = 1024 cp.async (4 per thread)
#pragma unroll
    for (int i = 0; i < 4; i++) {
        int e = i * 256 + tid;            // 0..1023
        int row = e >> 3;                 // 0..127
        int ch  = e & 7;                  // 16B chunk within 128B row
        uint32_t soff = row * 128 + ((ch ^ (row & 7)) << 4);
        cp_async16(sa + soff, &g_xh[(size_t)(m0 + row) * GEMM_K + k0 + ch * 8]);
    }
    // B: 256 rows x 8 chunks = 2048 cp.async (8 per thread)
#pragma unroll
    for (int i = 0; i < 8; i++) {
        int e = i * 256 + tid;            // 0..2047
        int row = e >> 3;                 // 0..255
        int ch  = e & 7;
        uint32_t soff = row * 128 + ((ch ^ (row & 7)) << 4);
        cp_async16(sB + soff, &g_wh[(size_t)(n0 + row) * GEMM_K + k0 + ch * 8]);
    }
}

__global__ void __launch_bounds__(256, 1)
gl_gemm(float* __restrict__ out) {
    extern __shared__ __align__(1024) char smem[];
    const uint32_t sbase = smem_u32(smem);
    const int tid  = threadIdx.x;
    const int wid  = tid >> 5;
    const int lane = tid & 31;
    const int m0 = blockIdx.y * BM;
    const int n0 = blockIdx.x * BN;
    const int warp_m = (wid >> 2) * 64;   // 0 or 64
    const int warp_n = (wid & 3) * 64;    // 0, 64, 128, 192

    float acc[4][8][4];
#pragma unroll
    for (int t = 0; t < 4; t++)
#pragma unroll
        for (int u = 0; u < 8; u++)
#pragma unroll
            for (int v = 0; v < 4; v++) acc[t][u][v] = 0.0f;

    // ---- prologue: fill 3 of 4 stages ----
#pragma unroll
    for (int s = 0; s < STAGES - 1; s++) {
        load_stage(sbase, s, s, m0, n0, tid);
        CP_COMMIT();
    }

    // ---- mainloop ----
#pragma unroll 1
    for (int j = 0; j < NKTILES; j++) {
        CP_WAIT(2);          // oldest pending group drained -> stage j complete
        __syncthreads();     // all warps done with stage (j-1); data visible

        // Issue next-stage loads FIRST so they overlap this stage's MMAs.
        // Target stage (j+3)&3 == (j-1)&3, freed by the barrier above.
        // Always commit (possibly empty) to keep 3 groups pending -> CP_WAIT(2)
        // stays meaningful through the tail.
        if (j + STAGES - 1 < NKTILES)
            load_stage(sbase, (j + STAGES - 1) & 3, j + STAGES - 1, m0, n0, tid);
        CP_COMMIT();

        const uint32_t sa = sbase + (j & 3) * STAGE_BYTES;
        const uint32_t sB = sa + A_STAGE_BYTES;

#pragma unroll
        for (int ks = 0; ks < 4; ks++) {
            // A fragments: 4 x (m16 x k16) via ldmatrix.x4
            uint32_t a[4][4];
            {
                const int r15 = lane & 15;
                const int ch  = ks * 2 + (lane >> 4);
#pragma unroll
                for (int t = 0; t < 4; t++) {
                    const int row = warp_m + t * 16 + r15;
                    const uint32_t addr =
                        sa + row * 128 + ((ch ^ (row & 7)) << 4);
                    LDSM_X4(a[t][0], a[t][1], a[t][2], a[t][3], addr);
                }
            }
            // B fragments: 8 x (n8 x k16); two n8-tiles per ldmatrix.x4
            uint32_t b[8][2];
            {
                const int nr = (lane & 7) + ((lane >> 4) << 3);
                const int ch = ks * 2 + ((lane >> 3) & 1);
#pragma unroll
                for (int p = 0; p < 4; p++) {
                    const int row = warp_n + p * 16 + nr;
                    const uint32_t addr =
                        sB + row * 128 + ((ch ^ (row & 7)) << 4);
                    LDSM_X4(b[2 * p][0], b[2 * p][1],
                            b[2 * p + 1][0], b[2 * p + 1][1], addr);
                }
            }
            // 32 MMAs
#pragma unroll
            for (int t = 0; t < 4; t++)
#pragma unroll
                for (int u = 0; u < 8; u++)
                    mma16816(acc[t][u], a[t], b[u]);
        }
    }

    // ---- epilogue: direct fp32 stores (float2, 32B-sector aligned) ----
    const int gq = lane >> 2;            // 0..7 (row within m16 tile)
    const int tq = lane & 3;             // 0..3 (col pair)
#pragma unroll
    for (int t = 0; t < 4; t++) {
#pragma unroll
        for (int u = 0; u < 8; u++) {
            const int r = m0 + warp_m + t * 16 + gq;
            const int c = n0 + warp_n + u * 8 + tq * 2;
            float2 v0 = make_float2(acc[t][u][0], acc[t][u][1]);
            float2 v1 = make_float2(acc[t][u][2], acc[t][u][3]);
            *reinterpret_cast<float2*>(&out[(size_t)r * GEMM_N + c]) = v0;
            *reinterpret_cast<float2*>(&out[(size_t)(r + 8) * GEMM_N + c]) = v1;
        }
    }
}

// ============================================================================
// Host side
// ============================================================================
extern "C" void kernel_launch(void* const* d_in, const int* in_sizes, int n_in,
                              void* d_out, int out_size) {
    const float* x     = (const float*)d_in[0];
    const int*   gidx  = (const int*)d_in[1];
    const float* scale = (const float*)d_in[2];
    float*       out   = (float*)d_out;

    // 1) prepass
    gl_convert_x<<<(GEMM_M * GEMM_K / 4) / 256, 256>>>(x);
    gl_dequant_w<<<(GEMM_N * GEMM_K / 4) / 256, 256>>>(gidx, scale);

    // 2) GEMM
    cudaFuncSetAttribute(gl_gemm, cudaFuncAttributeMaxDynamicSharedMemorySize,
                         SMEM_BYTES);
    dim3 grid(GEMM_N / BN, GEMM_M / BM);  // (32, 32)
    gl_gemm<<<grid, 256, SMEM_BYTES>>>(out);
}